// round 15
// baseline (speedup 1.0000x reference)
#include <cuda_runtime.h>
#include <cuda_fp16.h>
#include <cstdint>
#include <math.h>

// Problem constants
#define BSZ   4096
#define OBS   512
#define ACT_D 64
#define NT    10
#define NE    16
#define DREP  1024
#define DH    1024
#define DKE   512
#define XD    (OBS + ACT_D)   // 576
#define SW    (OBS + NT)      // 522

// ===================== helpers =====================
__device__ __forceinline__ uint32_t smem_u32(const void* p) {
    uint32_t a;
    asm("{ .reg .u64 t; cvta.to.shared.u64 t, %1; cvt.u32.u64 %0, t; }"
        : "=r"(a) : "l"(p));
    return a;
}
__device__ __forceinline__ void cp16(uint32_t dst, const void* src) {
    asm volatile("cp.async.cg.shared.global [%0], [%1], 16;" :: "r"(dst), "l"(src));
}
#define CP_COMMIT() asm volatile("cp.async.commit_group;" ::: "memory")
#define CP_WAIT0()  asm volatile("cp.async.wait_group 0;" ::: "memory")
#define CP_WAIT2()  asm volatile("cp.async.wait_group 2;" ::: "memory")

__device__ __forceinline__ void ldsm4(uint32_t* r, uint32_t addr) {
    asm volatile("ldmatrix.sync.aligned.m8n8.x4.shared.b16 {%0,%1,%2,%3}, [%4];"
                 : "=r"(r[0]), "=r"(r[1]), "=r"(r[2]), "=r"(r[3]) : "r"(addr));
}
// fp16 MMA, fp32 accumulate
__device__ __forceinline__ void mma16816(float* d, const uint32_t* a,
                                         uint32_t b0, uint32_t b1) {
    asm volatile(
        "mma.sync.aligned.m16n8k16.row.col.f32.f16.f16.f32 "
        "{%0,%1,%2,%3}, {%4,%5,%6,%7}, {%8,%9}, {%0,%1,%2,%3};"
        : "+f"(d[0]), "+f"(d[1]), "+f"(d[2]), "+f"(d[3])
        : "r"(a[0]), "r"(a[1]), "r"(a[2]), "r"(a[3]), "r"(b0), "r"(b1));
}

__device__ __forceinline__ void split2(float v, __half& h, __half& l) {
    h = __float2half(v);
    l = __float2half(v - __half2float(h));
}

// ===================== scratch (static device globals) =====================
__device__ __half g_xh[(size_t)BSZ * XD], g_xl[(size_t)BSZ * XD];
__device__ int   g_task[BSZ];
__device__ float g_qtab[NT * DKE];
__device__ float g_u[(size_t)NE * NT * DH];
__device__ float g_cvec[NE * NT];
__device__ __half g_rhh[(size_t)BSZ * DREP], g_rhl[(size_t)BSZ * DREP];
__device__ __half g_rsh[(size_t)BSZ * DREP];                          // single fp16
__device__ __half g_hkh[(size_t)NE * BSZ * DH];                       // single fp16
__device__ __half g_hvh[(size_t)NE * BSZ * DH];                       // single fp16
__device__ float g_vals[(size_t)NE * BSZ * DKE];
__device__ __half g_tih[(size_t)BSZ * DKE], g_til[(size_t)BSZ * DKE];
__device__ __half g_h1h[(size_t)BSZ * 512], g_h1l[(size_t)BSZ * 512];
__device__ float g_h2[(size_t)BSZ * 256];
__device__ float g_lrow[BSZ];
// transposed split weights ([N,K] fp16)
__device__ __half g_W0h[(size_t)DREP * XD],  g_W0l[(size_t)DREP * XD];
__device__ __half g_W1h[(size_t)DREP * DREP], g_W1l[(size_t)DREP * DREP];
__device__ __half g_Wk0h[(size_t)NE * DH * DREP];                     // h only
__device__ __half g_Wv0h[(size_t)NE * DH * DREP];                     // h only
__device__ __half g_Wv1h[(size_t)NE * DKE * DH];                      // h only
__device__ __half g_Wt0h[(size_t)512 * DKE], g_Wt0l[(size_t)512 * DKE];
__device__ __half g_Wt1h[(size_t)256 * 512], g_Wt1l[(size_t)256 * 512];

// ===================== prep: x split + task id ============================
__global__ void prep_kernel(const float* __restrict__ state,
                            const float* __restrict__ act,
                            __half* __restrict__ xh,
                            __half* __restrict__ xl,
                            int* __restrict__ task) {
    int b = blockIdx.x;
    int tid = threadIdx.x;
    for (int i = tid; i < XD; i += blockDim.x) {
        float v = (i < OBS) ? state[(size_t)b * SW + i] : act[(size_t)b * ACT_D + (i - OBS)];
        __half h, l;
        split2(v, h, l);
        xh[(size_t)b * XD + i] = h;
        xl[(size_t)b * XD + i] = l;
    }
    if (tid == 0) {
        float best = -1e30f; int idx = 0;
        for (int t = 0; t < NT; t++) {
            float v = state[(size_t)b * SW + OBS + t];
            if (v > best) { best = v; idx = t; }
        }
        task[b] = idx;
    }
}

// qtab[t][k] = tanh(emb[t][k])
__global__ void qtab_kernel(const float* __restrict__ emb, float* __restrict__ qtab) {
    int t = blockIdx.x;
    for (int k = threadIdx.x; k < DKE; k += blockDim.x)
        qtab[t * DKE + k] = tanhf(emb[t * DKE + k]);
}

// u[e][t][h] = sum_k Wk1[e][h][k] * qtab[t][k]
__global__ void upre_kernel(const float* __restrict__ Wk1,
                            const float* __restrict__ qtab,
                            float* __restrict__ u) {
    int z = blockIdx.y;               // e*NT + t
    int e = z / NT, t = z % NT;
    int wid = threadIdx.x >> 5, lane = threadIdx.x & 31;
    int h = blockIdx.x * 8 + wid;     // gridDim.x = DH/8
    const float* wr = Wk1 + ((size_t)e * DH + h) * DKE;
    const float* qr = qtab + t * DKE;
    float s = 0.0f;
#pragma unroll 4
    for (int k = lane; k < DKE; k += 32) s += wr[k] * qr[k];
#pragma unroll
    for (int off = 16; off > 0; off >>= 1) s += __shfl_down_sync(0xffffffffu, s, off);
    if (lane == 0) u[((size_t)e * NT + t) * DH + h] = s;
}

// cvec[e][t] = sum_k bk1[e][k] * qtab[t][k]
__global__ void cvec_kernel(const float* __restrict__ bk1,
                            const float* __restrict__ qtab,
                            float* __restrict__ cvec) {
    int e = blockIdx.x, t = blockIdx.y;
    __shared__ float sm[256];
    int tid = threadIdx.x;
    float s = 0.0f;
    for (int k = tid; k < DKE; k += 256) s += bk1[e * DKE + k] * qtab[t * DKE + k];
    sm[tid] = s;
    __syncthreads();
    for (int off = 128; off > 0; off >>= 1) {
        if (tid < off) sm[tid] += sm[tid + off];
        __syncthreads();
    }
    if (tid == 0) cvec[e * NT + t] = sm[0];
}

// ===================== ALL weight transposes in ONE launch ================
// Tile counts: W0 576 | W1 1024 | Wk0 16384 | Wv0 16384 | Wv1 8192
//              Wt0 256 | Wt1 128   (total 42944).  Wk1 handled by upre.
__global__ void wtrans_all(
    const float* __restrict__ W0, const float* __restrict__ W1,
    const float* __restrict__ Wk0, const float* __restrict__ Wv0,
    const float* __restrict__ Wv1,
    const float* __restrict__ Wt0, const float* __restrict__ Wt1,
    __half* W0h, __half* W0l, __half* W1h, __half* W1l,
    __half* Wk0h, __half* Wv0h, __half* Wv1h,
    __half* Wt0h, __half* Wt0l, __half* Wt1h, __half* Wt1l) {
    int t = blockIdx.x;
    const float* W; __half *Th, *Tl; int K, N;
    if (t < 576)                  { W = W0;  Th = W0h;  Tl = W0l;  K = XD;   N = DREP; }
    else if ((t -= 576) < 1024)   { W = W1;  Th = W1h;  Tl = W1l;  K = DREP; N = DREP; }
    else if ((t -= 1024) < 16384) { W = Wk0; Th = Wk0h; Tl = nullptr; K = DREP; N = DH; }
    else if ((t -= 16384) < 16384){ W = Wv0; Th = Wv0h; Tl = nullptr; K = DREP; N = DH; }
    else if ((t -= 16384) < 8192) { W = Wv1; Th = Wv1h; Tl = nullptr; K = DH;  N = DKE; }
    else if ((t -= 8192) < 256)   { W = Wt0; Th = Wt0h; Tl = Wt0l; K = DKE;  N = 512; }
    else                          { t -= 256; W = Wt1; Th = Wt1h; Tl = Wt1l; K = 512; N = 256; }
    int tpm = (K >> 5) * (N >> 5);
    int z = t / tpm, r = t % tpm;
    int kt = r / (N >> 5), nt = r % (N >> 5);
    W  += (size_t)z * K * N;
    Th += (size_t)z * K * N;
    if (Tl) Tl += (size_t)z * K * N;

    __shared__ float tsm[32][33];
    int n0 = nt * 32, k0 = kt * 32;
    int tx = threadIdx.x, ty = threadIdx.y;
    for (int i = ty; i < 32; i += 8)
        tsm[i][tx] = W[(size_t)(k0 + i) * N + n0 + tx];
    __syncthreads();
    for (int i = ty; i < 32; i += 8) {
        float v = tsm[tx][i];
        __half h = __float2half(v);
        Th[(size_t)(n0 + i) * K + k0 + tx] = h;
        if (Tl) Tl[(size_t)(n0 + i) * K + k0 + tx] = __float2half(v - __half2float(h));
    }
}

// ===================== mma.sync split-fp16 GEMM ============================
// Passes: AhBh always; +AhBl if BSPL; +AlBh if ASPL.
//   (1,1): exact 3-pass | (1,0)/(0,1): 2-pass | (0,0): 1-pass pure fp16.
// OUT: 0 = fp32 Cf, 1 = split (Ch, Cl), 2 = single fp16 Ch
// CTA tile 128x128, BK=32, 3-stage cp.async pipeline, 2 CTAs/SM.

#define STG 32768            // Ah 8K | Al 8K | Bh 8K | Bl 8K
#define OFF_AH 0
#define OFF_AL 8192
#define OFF_BH 16384
#define OFF_BL 24576
#define SM_REQ (3 * STG)

__device__ __forceinline__ uint32_t swz(int r, int c) {
    return (uint32_t)(r * 64 + ((c ^ ((r >> 1) & 3)) << 4));
}

template <bool ASPL, bool BSPL, bool RELU, int OUT>
__global__ void __launch_bounds__(256, 2)
gemm_mma(const __half* __restrict__ Ah, const __half* __restrict__ Al,
         const __half* __restrict__ Bh, const __half* __restrict__ Bl,
         const float* __restrict__ bias,
         float* __restrict__ Cf, __half* __restrict__ Ch, __half* __restrict__ Cl,
         int N, int K, long sA, long sB, long sBias, long sC) {
    extern __shared__ char sm_raw[];
    uint32_t sb = smem_u32(sm_raw);

    int tid = threadIdx.x, lane = tid & 31, wid = tid >> 5;
    int z = blockIdx.z;
    const char* aH = (const char*)(Ah + (size_t)z * sA);
    const char* aL = ASPL ? (const char*)(Al + (size_t)z * sA) : nullptr;
    const char* bH = (const char*)(Bh + (size_t)z * sB);
    const char* bL = BSPL ? (const char*)(Bl + (size_t)z * sB) : nullptr;
    bias += (size_t)z * sBias;
    size_t coff = (size_t)z * sC;

    int m0 = blockIdx.y * 128, n0 = blockIdx.x * 128;
    int wm = wid & 1, wn = wid >> 1;       // 2 x 4 warps, warp tile 64x32

    size_t rsb = (size_t)K * 2;
    aH += (size_t)m0 * rsb;
    if (ASPL) aL += (size_t)m0 * rsb;
    bH += (size_t)n0 * rsb;
    if (BSPL) bL += (size_t)n0 * rsb;

    float acc[4][4][4];
#pragma unroll
    for (int i = 0; i < 4; i++)
#pragma unroll
        for (int j = 0; j < 4; j++)
#pragma unroll
            for (int q = 0; q < 4; q++) acc[i][j][q] = 0.0f;

    int NC = K >> 5;

    auto load_stage = [&](int c, int buf) {
        uint32_t s = sb + buf * STG;
        size_t gk = (size_t)c * 64;
#pragma unroll
        for (int p = tid; p < 512; p += 256) {
            int r = p >> 2, ch = p & 3;
            uint32_t off = swz(r, ch);
            size_t g = (size_t)r * rsb + gk + ch * 16;
            cp16(s + OFF_AH + off, aH + g);
            if (ASPL) cp16(s + OFF_AL + off, aL + g);
            cp16(s + OFF_BH + off, bH + g);
            if (BSPL) cp16(s + OFF_BL + off, bL + g);
        }
    };

    load_stage(0, 0); CP_COMMIT();
    load_stage(1, 1); CP_COMMIT();

    int arow = wm * 64 + (lane & 7) + ((lane >> 3) & 1) * 8;
    int achk_b = (lane >> 4);
    int brow = wn * 32 + (lane & 7) + (lane >> 4) * 8;
    int bchk_b = ((lane >> 3) & 1);

    for (int c = 0; c < NC; c++) {
        if (c + 2 < NC) load_stage(c + 2, (c + 2) % 3);
        CP_COMMIT();
        CP_WAIT2();            // stage c resident
        __syncthreads();

        uint32_t s = sb + (c % 3) * STG;
#pragma unroll
        for (int ks = 0; ks < 2; ks++) {
            int achk = ks * 2 + achk_b;
            int bchk = ks * 2 + bchk_b;
            // ---- pass 1: Ah * Bh ----
            uint32_t fah[4][4], fbh[2][4];
#pragma unroll
            for (int mt = 0; mt < 4; mt++)
                ldsm4(fah[mt], s + OFF_AH + swz(arow + mt * 16, achk));
#pragma unroll
            for (int nt2 = 0; nt2 < 2; nt2++)
                ldsm4(fbh[nt2], s + OFF_BH + swz(brow + nt2 * 16, bchk));
#pragma unroll
            for (int mt = 0; mt < 4; mt++)
#pragma unroll
                for (int nt2 = 0; nt2 < 2; nt2++) {
                    mma16816(acc[mt][nt2 * 2 + 0], fah[mt], fbh[nt2][0], fbh[nt2][1]);
                    mma16816(acc[mt][nt2 * 2 + 1], fah[mt], fbh[nt2][2], fbh[nt2][3]);
                }
            // ---- pass 2: Ah * Bl ----
            if (BSPL) {
                uint32_t fbl[2][4];
#pragma unroll
                for (int nt2 = 0; nt2 < 2; nt2++)
                    ldsm4(fbl[nt2], s + OFF_BL + swz(brow + nt2 * 16, bchk));
#pragma unroll
                for (int mt = 0; mt < 4; mt++)
#pragma unroll
                    for (int nt2 = 0; nt2 < 2; nt2++) {
                        mma16816(acc[mt][nt2 * 2 + 0], fah[mt], fbl[nt2][0], fbl[nt2][1]);
                        mma16816(acc[mt][nt2 * 2 + 1], fah[mt], fbl[nt2][2], fbl[nt2][3]);
                    }
            }
            // ---- pass 3: Al * Bh ----
            if (ASPL) {
                uint32_t fal[4][4];
#pragma unroll
                for (int mt = 0; mt < 4; mt++)
                    ldsm4(fal[mt], s + OFF_AL + swz(arow + mt * 16, achk));
#pragma unroll
                for (int mt = 0; mt < 4; mt++)
#pragma unroll
                    for (int nt2 = 0; nt2 < 2; nt2++) {
                        mma16816(acc[mt][nt2 * 2 + 0], fal[mt], fbh[nt2][0], fbh[nt2][1]);
                        mma16816(acc[mt][nt2 * 2 + 1], fal[mt], fbh[nt2][2], fbh[nt2][3]);
                    }
            }
        }
        __syncthreads();
    }

    // ---- epilogue ----
    int mbase = m0 + wm * 64 + (lane >> 2);
    int nbase = n0 + wn * 32 + (lane & 3) * 2;
#pragma unroll
    for (int nt = 0; nt < 4; nt++) {
        int n = nbase + nt * 8;
        float b0 = bias[n], b1 = bias[n + 1];
#pragma unroll
        for (int mt = 0; mt < 4; mt++) {
            int m = mbase + mt * 16;
            float v00 = acc[mt][nt][0] + b0, v01 = acc[mt][nt][1] + b1;
            float v10 = acc[mt][nt][2] + b0, v11 = acc[mt][nt][3] + b1;
            if (RELU) {
                v00 = fmaxf(v00, 0.0f); v01 = fmaxf(v01, 0.0f);
                v10 = fmaxf(v10, 0.0f); v11 = fmaxf(v11, 0.0f);
            }
            if (OUT == 1) {
                __half2 h2a, l2a, h2b, l2b;
                split2(v00, h2a.x, l2a.x); split2(v01, h2a.y, l2a.y);
                split2(v10, h2b.x, l2b.x); split2(v11, h2b.y, l2b.y);
                *(__half2*)(Ch + coff + (size_t)m * N + n)       = h2a;
                *(__half2*)(Cl + coff + (size_t)m * N + n)       = l2a;
                *(__half2*)(Ch + coff + (size_t)(m + 8) * N + n) = h2b;
                *(__half2*)(Cl + coff + (size_t)(m + 8) * N + n) = l2b;
            } else if (OUT == 2) {
                *(__half2*)(Ch + coff + (size_t)m * N + n) =
                    __floats2half2_rn(v00, v01);
                *(__half2*)(Ch + coff + (size_t)(m + 8) * N + n) =
                    __floats2half2_rn(v10, v11);
            } else {
                *(float2*)(Cf + coff + (size_t)m * N + n)       = make_float2(v00, v01);
                *(float2*)(Cf + coff + (size_t)(m + 8) * N + n) = make_float2(v10, v11);
            }
        }
    }
}

// ===================== attention: logits from hk, softmax, mixture ========
__global__ void attn_kernel(const int* __restrict__ task,
                            const __half* __restrict__ hkh,
                            const float* __restrict__ u,
                            const float* __restrict__ cvec,
                            const float* __restrict__ vals,
                            __half* __restrict__ tih,
                            __half* __restrict__ til,
                            float* __restrict__ loss_row) {
    int b = blockIdx.x;
    int tid = threadIdx.x;
    int wid = tid >> 5, lane = tid & 31;
    int t = task[b];

    float part[NE];
#pragma unroll
    for (int e = 0; e < NE; e++) part[e] = 0.0f;
    for (int h = tid; h < DH; h += 256) {
#pragma unroll
        for (int e = 0; e < NE; e++) {
            float hv_ = __half2float(hkh[((size_t)e * BSZ + b) * DH + h]);
            part[e] += hv_ * u[((size_t)e * NT + t) * DH + h];
        }
    }
#pragma unroll
    for (int e = 0; e < NE; e++) {
#pragma unroll
        for (int off = 16; off > 0; off >>= 1)
            part[e] += __shfl_down_sync(0xffffffffu, part[e], off);
    }
    __shared__ float warpsum[8][NE];
    __shared__ float attn_s[NE];
    if (lane == 0) {
#pragma unroll
        for (int e = 0; e < NE; e++) warpsum[wid][e] = part[e];
    }
    __syncthreads();
    if (tid == 0) {
        float logits[NE];
#pragma unroll
        for (int e = 0; e < NE; e++) {
            float s = cvec[e * NT + t];
            for (int w = 0; w < 8; w++) s += warpsum[w][e];
            logits[e] = s;
        }
        float mx = logits[0];
#pragma unroll
        for (int e = 1; e < NE; e++) mx = fmaxf(mx, logits[e]);
        float den = 0.0f, ex[NE];
#pragma unroll
        for (int e = 0; e < NE; e++) { ex[e] = expf(logits[e] - mx); den += ex[e]; }
        float inv = 1.0f / den;
        float lsum = 0.0f;
#pragma unroll
        for (int e = 0; e < NE; e++) {
            float a = ex[e] * inv;
            attn_s[e] = a;
            float lg = logf(a + 1e-10f);
            lg = fminf(fmaxf(lg, -6.0f), 0.0f);
            lsum += lg;
        }
        loss_row[b] = lsum;
    }
    __syncthreads();
    for (int k = tid; k < DKE; k += 256) {
        float acc = 0.0f;
#pragma unroll
        for (int e = 0; e < NE; e++)
            acc += attn_s[e] * vals[((size_t)e * BSZ + b) * DKE + k];
        __half h, l;
        split2(acc, h, l);
        tih[(size_t)b * DKE + k] = h;
        til[(size_t)b * DKE + k] = l;
    }
}

// ===================== q head + loss =====================================
__global__ void qhead_kernel(const float* __restrict__ h2,
                             const float* __restrict__ Wt2,
                             const float* __restrict__ bt2,
                             float* __restrict__ out) {
    int warp = (blockIdx.x * blockDim.x + threadIdx.x) >> 5;
    int lane = threadIdx.x & 31;
    if (warp >= BSZ) return;
    float s = 0.0f;
#pragma unroll
    for (int k = lane; k < 256; k += 32)
        s += h2[(size_t)warp * 256 + k] * Wt2[k];
#pragma unroll
    for (int off = 16; off > 0; off >>= 1)
        s += __shfl_down_sync(0xffffffffu, s, off);
    if (lane == 0) out[warp] = s + bt2[0];
}

__global__ void loss_kernel(const float* __restrict__ loss_row,
                            float* __restrict__ out, int out_size) {
    __shared__ float sm[256];
    int tid = threadIdx.x;
    float s = 0.0f;
    for (int i = tid; i < BSZ; i += 256) s += loss_row[i];
    sm[tid] = s;
    __syncthreads();
    for (int off = 128; off > 0; off >>= 1) {
        if (tid < off) sm[tid] += sm[tid + off];
        __syncthreads();
    }
    if (tid == 0 && out_size > BSZ)
        out[BSZ] = -(sm[0] / (float)BSZ) * 0.3f;
}

// ===================== launch =============================================
#define SYM(var, sym) cudaGetSymbolAddress((void**)&var, sym)

extern "C" void kernel_launch(void* const* d_in, const int* in_sizes, int n_in,
                              void* d_out, int out_size) {
    const float* state  = (const float*)d_in[0];
    const float* act    = (const float*)d_in[1];
    const float* rep_W0 = (const float*)d_in[2];
    const float* rep_b0 = (const float*)d_in[3];
    const float* rep_W1 = (const float*)d_in[4];
    const float* rep_b1 = (const float*)d_in[5];
    const float* emb    = (const float*)d_in[6];
    const float* Wk0    = (const float*)d_in[7];
    const float* bk0    = (const float*)d_in[8];
    const float* Wk1    = (const float*)d_in[9];
    const float* bk1    = (const float*)d_in[10];
    const float* Wv0    = (const float*)d_in[11];
    const float* bv0    = (const float*)d_in[12];
    const float* Wv1    = (const float*)d_in[13];
    const float* bv1    = (const float*)d_in[14];
    const float* Wt0    = (const float*)d_in[15];
    const float* bt0    = (const float*)d_in[16];
    const float* Wt1    = (const float*)d_in[17];
    const float* bt1    = (const float*)d_in[18];
    const float* Wt2    = (const float*)d_in[19];
    const float* bt2    = (const float*)d_in[20];
    float* out = (float*)d_out;

    __half *xh, *xl, *rhh, *rhl, *rsh, *hkh, *hvh;
    __half *tih, *til, *h1h, *h1l;
    __half *W0h, *W0l, *W1h, *W1l, *Wk0h, *Wv0h, *Wv1h;
    __half *Wt0h, *Wt0l, *Wt1h, *Wt1l;
    float *qtab, *u, *cvec, *vals, *h2, *lrow;
    int* task;
    SYM(xh, g_xh);   SYM(xl, g_xl);   SYM(task, g_task);
    SYM(qtab, g_qtab); SYM(u, g_u);   SYM(cvec, g_cvec);
    SYM(rhh, g_rhh); SYM(rhl, g_rhl); SYM(rsh, g_rsh);
    SYM(hkh, g_hkh); SYM(hvh, g_hvh);
    SYM(vals, g_vals);
    SYM(tih, g_tih); SYM(til, g_til); SYM(h1h, g_h1h); SYM(h1l, g_h1l);
    SYM(h2, g_h2);   SYM(lrow, g_lrow);
    SYM(W0h, g_W0h); SYM(W0l, g_W0l); SYM(W1h, g_W1h); SYM(W1l, g_W1l);
    SYM(Wk0h, g_Wk0h); SYM(Wv0h, g_Wv0h); SYM(Wv1h, g_Wv1h);
    SYM(Wt0h, g_Wt0h); SYM(Wt0l, g_Wt0l); SYM(Wt1h, g_Wt1h); SYM(Wt1l, g_Wt1l);

    cudaFuncSetAttribute(gemm_mma<true, true, true, 1>,   cudaFuncAttributeMaxDynamicSharedMemorySize, SM_REQ);
    cudaFuncSetAttribute(gemm_mma<true, true, false, 2>,  cudaFuncAttributeMaxDynamicSharedMemorySize, SM_REQ);
    cudaFuncSetAttribute(gemm_mma<false, false, true, 2>, cudaFuncAttributeMaxDynamicSharedMemorySize, SM_REQ);
    cudaFuncSetAttribute(gemm_mma<false, false, false, 0>,cudaFuncAttributeMaxDynamicSharedMemorySize, SM_REQ);
    cudaFuncSetAttribute(gemm_mma<true, true, true, 0>,   cudaFuncAttributeMaxDynamicSharedMemorySize, SM_REQ);

    // prep / precompute
    prep_kernel<<<BSZ, 256>>>(state, act, xh, xl, task);
    qtab_kernel<<<NT, 256>>>(emb, qtab);
    upre_kernel<<<dim3(DH / 8, NE * NT), 256>>>(Wk1, qtab, u);
    cvec_kernel<<<dim3(NE, NT), 256>>>(bk1, qtab, cvec);
    wtrans_all<<<42944, dim3(32, 8)>>>(
        rep_W0, rep_W1, Wk0, Wv0, Wv1, Wt0, Wt1,
        W0h, W0l, W1h, W1l, Wk0h, Wv0h, Wv1h,
        Wt0h, Wt0l, Wt1h, Wt1l);

    // rep MLP (exact 3-pass; final output single fp16 = the one rep rounding)
    gemm_mma<true, true, true, 1><<<dim3(DREP / 128, BSZ / 128, 1), 256, SM_REQ>>>(
        xh, xl, W0h, W0l, rep_b0, nullptr, rhh, rhl, DREP, XD, 0, 0, 0, 0);
    gemm_mma<true, true, false, 2><<<dim3(DREP / 128, BSZ / 128, 1), 256, SM_REQ>>>(
        rhh, rhl, W1h, W1l, rep_b1, nullptr, rsh, nullptr, DREP, DREP, 0, 0, 0, 0);
    // expert layer 1: both 1-pass pure fp16
    gemm_mma<false, false, true, 2><<<dim3(DH / 128, BSZ / 128, NE), 256, SM_REQ>>>(
        rsh, nullptr, Wk0h, nullptr, bk0, nullptr, hkh, nullptr, DH, DREP,
        0, (long)DH * DREP, DH, (long)BSZ * DH);
    gemm_mma<false, false, true, 2><<<dim3(DH / 128, BSZ / 128, NE), 256, SM_REQ>>>(
        rsh, nullptr, Wv0h, nullptr, bv0, nullptr, hvh, nullptr, DH, DREP,
        0, (long)DH * DREP, DH, (long)BSZ * DH);
    // expert layer 2, V only: 1-pass pure fp16 -> fp32 vals
    gemm_mma<false, false, false, 0><<<dim3(DKE / 128, BSZ / 128, NE), 256, SM_REQ>>>(
        hvh, nullptr, Wv1h, nullptr, bv1, vals, nullptr, nullptr, DKE, DH,
        (long)BSZ * DH, (long)DKE * DH, DKE, (long)BSZ * DKE);
    // attention: logits from hk via u, softmax, mixture
    attn_kernel<<<BSZ, 256>>>(task, hkh, u, cvec, vals, tih, til, lrow);
    // tower (exact 3-pass)
    gemm_mma<true, true, true, 1><<<dim3(512 / 128, BSZ / 128, 1), 256, SM_REQ>>>(
        tih, til, Wt0h, Wt0l, bt0, nullptr, h1h, h1l, 512, DKE, 0, 0, 0, 0);
    gemm_mma<true, true, true, 0><<<dim3(256 / 128, BSZ / 128, 1), 256, SM_REQ>>>(
        h1h, h1l, Wt1h, Wt1l, bt1, h2, nullptr, nullptr, 256, 512, 0, 0, 0, 0);
    // head + loss
    qhead_kernel<<<(BSZ * 32 + 255) / 256, 256>>>(h2, Wt2, bt2, out);
    loss_kernel<<<1, 256>>>(lrow, out, out_size);
}

// round 16
// speedup vs baseline: 1.1513x; 1.1513x over previous
#include <cuda_runtime.h>
#include <cuda_fp16.h>
#include <cstdint>
#include <math.h>

// Problem constants
#define BSZ   4096
#define OBS   512
#define ACT_D 64
#define NT    10
#define NE    16
#define DREP  1024
#define DH    1024
#define DKE   512
#define XD    (OBS + ACT_D)   // 576
#define SW    (OBS + NT)      // 522

// ===================== helpers =====================
__device__ __forceinline__ uint32_t smem_u32(const void* p) {
    uint32_t a;
    asm("{ .reg .u64 t; cvta.to.shared.u64 t, %1; cvt.u32.u64 %0, t; }"
        : "=r"(a) : "l"(p));
    return a;
}
__device__ __forceinline__ void cp16(uint32_t dst, const void* src) {
    asm volatile("cp.async.cg.shared.global [%0], [%1], 16;" :: "r"(dst), "l"(src));
}
#define CP_COMMIT() asm volatile("cp.async.commit_group;" ::: "memory")
#define CP_WAIT1()  asm volatile("cp.async.wait_group 1;" ::: "memory")

__device__ __forceinline__ void ldsm4(uint32_t* r, uint32_t addr) {
    asm volatile("ldmatrix.sync.aligned.m8n8.x4.shared.b16 {%0,%1,%2,%3}, [%4];"
                 : "=r"(r[0]), "=r"(r[1]), "=r"(r[2]), "=r"(r[3]) : "r"(addr));
}
// fp16 MMA, fp32 accumulate
__device__ __forceinline__ void mma16816(float* d, const uint32_t* a,
                                         uint32_t b0, uint32_t b1) {
    asm volatile(
        "mma.sync.aligned.m16n8k16.row.col.f32.f16.f16.f32 "
        "{%0,%1,%2,%3}, {%4,%5,%6,%7}, {%8,%9}, {%0,%1,%2,%3};"
        : "+f"(d[0]), "+f"(d[1]), "+f"(d[2]), "+f"(d[3])
        : "r"(a[0]), "r"(a[1]), "r"(a[2]), "r"(a[3]), "r"(b0), "r"(b1));
}

__device__ __forceinline__ void split2(float v, __half& h, __half& l) {
    h = __float2half(v);
    l = __float2half(v - __half2float(h));
}

// ===================== scratch (static device globals) =====================
__device__ __half g_xh[(size_t)BSZ * XD], g_xl[(size_t)BSZ * XD];
__device__ int   g_task[BSZ];
__device__ float g_qtab[NT * DKE];
__device__ float g_u[(size_t)NE * NT * DH];
__device__ float g_cvec[NE * NT];
__device__ __half g_rhh[(size_t)BSZ * DREP], g_rhl[(size_t)BSZ * DREP];
__device__ __half g_rsh[(size_t)BSZ * DREP], g_rsl[(size_t)BSZ * DREP];
__device__ __half g_hkh[(size_t)NE * BSZ * DH];                       // single fp16
__device__ __half g_hvh[(size_t)NE * BSZ * DH];                       // single fp16
__device__ float g_vals[(size_t)NE * BSZ * DKE];
__device__ __half g_tih[(size_t)BSZ * DKE], g_til[(size_t)BSZ * DKE];
__device__ __half g_h1h[(size_t)BSZ * 512], g_h1l[(size_t)BSZ * 512];
__device__ float g_h2[(size_t)BSZ * 256];
__device__ float g_lrow[BSZ];
// transposed split weights ([N,K] fp16)
__device__ __half g_W0h[(size_t)DREP * XD],  g_W0l[(size_t)DREP * XD];
__device__ __half g_W1h[(size_t)DREP * DREP], g_W1l[(size_t)DREP * DREP];
__device__ __half g_Wk0h[(size_t)NE * DH * DREP];                     // h only
__device__ __half g_Wv0h[(size_t)NE * DH * DREP];                     // h only
__device__ __half g_Wv1h[(size_t)NE * DKE * DH], g_Wv1l[(size_t)NE * DKE * DH];
__device__ __half g_Wt0h[(size_t)512 * DKE], g_Wt0l[(size_t)512 * DKE];
__device__ __half g_Wt1h[(size_t)256 * 512], g_Wt1l[(size_t)256 * 512];

// ===================== prep: x split + task id ============================
__global__ void prep_kernel(const float* __restrict__ state,
                            const float* __restrict__ act,
                            __half* __restrict__ xh,
                            __half* __restrict__ xl,
                            int* __restrict__ task) {
    int b = blockIdx.x;
    int tid = threadIdx.x;
    for (int i = tid; i < XD; i += blockDim.x) {
        float v = (i < OBS) ? state[(size_t)b * SW + i] : act[(size_t)b * ACT_D + (i - OBS)];
        __half h, l;
        split2(v, h, l);
        xh[(size_t)b * XD + i] = h;
        xl[(size_t)b * XD + i] = l;
    }
    if (tid == 0) {
        float best = -1e30f; int idx = 0;
        for (int t = 0; t < NT; t++) {
            float v = state[(size_t)b * SW + OBS + t];
            if (v > best) { best = v; idx = t; }
        }
        task[b] = idx;
    }
}

// qtab[t][k] = tanh(emb[t][k])
__global__ void qtab_kernel(const float* __restrict__ emb, float* __restrict__ qtab) {
    int t = blockIdx.x;
    for (int k = threadIdx.x; k < DKE; k += blockDim.x)
        qtab[t * DKE + k] = tanhf(emb[t * DKE + k]);
}

// u[e][t][h] = sum_k Wk1[e][h][k] * qtab[t][k]
__global__ void upre_kernel(const float* __restrict__ Wk1,
                            const float* __restrict__ qtab,
                            float* __restrict__ u) {
    int z = blockIdx.y;               // e*NT + t
    int e = z / NT, t = z % NT;
    int wid = threadIdx.x >> 5, lane = threadIdx.x & 31;
    int h = blockIdx.x * 8 + wid;     // gridDim.x = DH/8
    const float* wr = Wk1 + ((size_t)e * DH + h) * DKE;
    const float* qr = qtab + t * DKE;
    float s = 0.0f;
#pragma unroll 4
    for (int k = lane; k < DKE; k += 32) s += wr[k] * qr[k];
#pragma unroll
    for (int off = 16; off > 0; off >>= 1) s += __shfl_down_sync(0xffffffffu, s, off);
    if (lane == 0) u[((size_t)e * NT + t) * DH + h] = s;
}

// cvec[e][t] = sum_k bk1[e][k] * qtab[t][k]
__global__ void cvec_kernel(const float* __restrict__ bk1,
                            const float* __restrict__ qtab,
                            float* __restrict__ cvec) {
    int e = blockIdx.x, t = blockIdx.y;
    __shared__ float sm[256];
    int tid = threadIdx.x;
    float s = 0.0f;
    for (int k = tid; k < DKE; k += 256) s += bk1[e * DKE + k] * qtab[t * DKE + k];
    sm[tid] = s;
    __syncthreads();
    for (int off = 128; off > 0; off >>= 1) {
        if (tid < off) sm[tid] += sm[tid + off];
        __syncthreads();
    }
    if (tid == 0) cvec[e * NT + t] = sm[0];
}

// ===================== ALL weight transposes in ONE launch ================
// Tile counts: W0 576 | W1 1024 | Wk0 16384 | Wv0 16384 | Wv1 8192
//              Wt0 256 | Wt1 128   (total 42944).  Wk1 handled by upre.
__global__ void wtrans_all(
    const float* __restrict__ W0, const float* __restrict__ W1,
    const float* __restrict__ Wk0, const float* __restrict__ Wv0,
    const float* __restrict__ Wv1,
    const float* __restrict__ Wt0, const float* __restrict__ Wt1,
    __half* W0h, __half* W0l, __half* W1h, __half* W1l,
    __half* Wk0h, __half* Wv0h,
    __half* Wv1h, __half* Wv1l,
    __half* Wt0h, __half* Wt0l, __half* Wt1h, __half* Wt1l) {
    int t = blockIdx.x;
    const float* W; __half *Th, *Tl; int K, N;
    if (t < 576)                  { W = W0;  Th = W0h;  Tl = W0l;  K = XD;   N = DREP; }
    else if ((t -= 576) < 1024)   { W = W1;  Th = W1h;  Tl = W1l;  K = DREP; N = DREP; }
    else if ((t -= 1024) < 16384) { W = Wk0; Th = Wk0h; Tl = nullptr; K = DREP; N = DH; }
    else if ((t -= 16384) < 16384){ W = Wv0; Th = Wv0h; Tl = nullptr; K = DREP; N = DH; }
    else if ((t -= 16384) < 8192) { W = Wv1; Th = Wv1h; Tl = Wv1l; K = DH;   N = DKE; }
    else if ((t -= 8192) < 256)   { W = Wt0; Th = Wt0h; Tl = Wt0l; K = DKE;  N = 512; }
    else                          { t -= 256; W = Wt1; Th = Wt1h; Tl = Wt1l; K = 512; N = 256; }
    int tpm = (K >> 5) * (N >> 5);
    int z = t / tpm, r = t % tpm;
    int kt = r / (N >> 5), nt = r % (N >> 5);
    W  += (size_t)z * K * N;
    Th += (size_t)z * K * N;
    if (Tl) Tl += (size_t)z * K * N;

    __shared__ float tsm[32][33];
    int n0 = nt * 32, k0 = kt * 32;
    int tx = threadIdx.x, ty = threadIdx.y;
    for (int i = ty; i < 32; i += 8)
        tsm[i][tx] = W[(size_t)(k0 + i) * N + n0 + tx];
    __syncthreads();
    for (int i = ty; i < 32; i += 8) {
        float v = tsm[tx][i];
        __half h = __float2half(v);
        Th[(size_t)(n0 + i) * K + k0 + tx] = h;
        if (Tl) Tl[(size_t)(n0 + i) * K + k0 + tx] = __float2half(v - __half2float(h));
    }
}

// ===================== mma.sync split-fp16 GEMM ============================
// Passes: AhBh always; +AhBl if BSPL; +AlBh if ASPL.
//   (1,1): exact 3-pass | (1,0)/(0,1): 2-pass | (0,0): 1-pass pure fp16.
// OUT: 0 = fp32 Cf, 1 = split (Ch, Cl), 2 = single fp16 Ch
// CTA tile 128x128, BK=32, 3-stage cp.async pipeline, ONE barrier per chunk:
//   iter c:  wait(newest-1) -> sync -> issue load(c+2) -> commit -> consume(c)
// The single barrier both publishes stage c (all threads ran wait_group 1
// before it) and proves all warps finished reading buffer (c-1)%3 (written
// next by load(c+2)).  One commit per iter keeps "newest group = #c+1".

#define STG 32768            // Ah 8K | Al 8K | Bh 8K | Bl 8K
#define OFF_AH 0
#define OFF_AL 8192
#define OFF_BH 16384
#define OFF_BL 24576
#define SM_REQ (3 * STG)

__device__ __forceinline__ uint32_t swz(int r, int c) {
    return (uint32_t)(r * 64 + ((c ^ ((r >> 1) & 3)) << 4));
}

template <bool ASPL, bool BSPL, bool RELU, int OUT>
__global__ void __launch_bounds__(256, 2)
gemm_mma(const __half* __restrict__ Ah, const __half* __restrict__ Al,
         const __half* __restrict__ Bh, const __half* __restrict__ Bl,
         const float* __restrict__ bias,
         float* __restrict__ Cf, __half* __restrict__ Ch, __half* __restrict__ Cl,
         int N, int K, long sA, long sB, long sBias, long sC) {
    extern __shared__ char sm_raw[];
    uint32_t sb = smem_u32(sm_raw);

    int tid = threadIdx.x, lane = tid & 31, wid = tid >> 5;
    int z = blockIdx.z;
    const char* aH = (const char*)(Ah + (size_t)z * sA);
    const char* aL = ASPL ? (const char*)(Al + (size_t)z * sA) : nullptr;
    const char* bH = (const char*)(Bh + (size_t)z * sB);
    const char* bL = BSPL ? (const char*)(Bl + (size_t)z * sB) : nullptr;
    bias += (size_t)z * sBias;
    size_t coff = (size_t)z * sC;

    int m0 = blockIdx.y * 128, n0 = blockIdx.x * 128;
    int wm = wid & 1, wn = wid >> 1;       // 2 x 4 warps, warp tile 64x32

    size_t rsb = (size_t)K * 2;
    aH += (size_t)m0 * rsb;
    if (ASPL) aL += (size_t)m0 * rsb;
    bH += (size_t)n0 * rsb;
    if (BSPL) bL += (size_t)n0 * rsb;

    float acc[4][4][4];
#pragma unroll
    for (int i = 0; i < 4; i++)
#pragma unroll
        for (int j = 0; j < 4; j++)
#pragma unroll
            for (int q = 0; q < 4; q++) acc[i][j][q] = 0.0f;

    int NC = K >> 5;

    auto load_stage = [&](int c, int buf) {
        uint32_t s = sb + buf * STG;
        size_t gk = (size_t)c * 64;
#pragma unroll
        for (int p = tid; p < 512; p += 256) {
            int r = p >> 2, ch = p & 3;
            uint32_t off = swz(r, ch);
            size_t g = (size_t)r * rsb + gk + ch * 16;
            cp16(s + OFF_AH + off, aH + g);
            if (ASPL) cp16(s + OFF_AL + off, aL + g);
            cp16(s + OFF_BH + off, bH + g);
            if (BSPL) cp16(s + OFF_BL + off, bL + g);
        }
    };

    // prologue: groups #0 (stage 0), #1 (stage 1)
    load_stage(0, 0); CP_COMMIT();
    load_stage(1, 1); CP_COMMIT();

    int arow = wm * 64 + (lane & 7) + ((lane >> 3) & 1) * 8;
    int achk_b = (lane >> 4);
    int brow = wn * 32 + (lane & 7) + (lane >> 4) * 8;
    int bchk_b = ((lane >> 3) & 1);

    for (int c = 0; c < NC; c++) {
        // newest committed group = #c+1; wait_group 1 => group #c (stage c) done
        CP_WAIT1();
        __syncthreads();
        if (c + 2 < NC) load_stage(c + 2, (c + 2) % 3);
        CP_COMMIT();   // group #c+2 (possibly empty)

        uint32_t s = sb + (c % 3) * STG;
#pragma unroll
        for (int ks = 0; ks < 2; ks++) {
            int achk = ks * 2 + achk_b;
            int bchk = ks * 2 + bchk_b;
            // ---- pass 1: Ah * Bh ----
            uint32_t fah[4][4], fbh[2][4];
#pragma unroll
            for (int mt = 0; mt < 4; mt++)
                ldsm4(fah[mt], s + OFF_AH + swz(arow + mt * 16, achk));
#pragma unroll
            for (int nt2 = 0; nt2 < 2; nt2++)
                ldsm4(fbh[nt2], s + OFF_BH + swz(brow + nt2 * 16, bchk));
#pragma unroll
            for (int mt = 0; mt < 4; mt++)
#pragma unroll
                for (int nt2 = 0; nt2 < 2; nt2++) {
                    mma16816(acc[mt][nt2 * 2 + 0], fah[mt], fbh[nt2][0], fbh[nt2][1]);
                    mma16816(acc[mt][nt2 * 2 + 1], fah[mt], fbh[nt2][2], fbh[nt2][3]);
                }
            // ---- pass 2: Ah * Bl ----
            if (BSPL) {
                uint32_t fbl[2][4];
#pragma unroll
                for (int nt2 = 0; nt2 < 2; nt2++)
                    ldsm4(fbl[nt2], s + OFF_BL + swz(brow + nt2 * 16, bchk));
#pragma unroll
                for (int mt = 0; mt < 4; mt++)
#pragma unroll
                    for (int nt2 = 0; nt2 < 2; nt2++) {
                        mma16816(acc[mt][nt2 * 2 + 0], fah[mt], fbl[nt2][0], fbl[nt2][1]);
                        mma16816(acc[mt][nt2 * 2 + 1], fah[mt], fbl[nt2][2], fbl[nt2][3]);
                    }
            }
            // ---- pass 3: Al * Bh ----
            if (ASPL) {
                uint32_t fal[4][4];
#pragma unroll
                for (int mt = 0; mt < 4; mt++)
                    ldsm4(fal[mt], s + OFF_AL + swz(arow + mt * 16, achk));
#pragma unroll
                for (int mt = 0; mt < 4; mt++)
#pragma unroll
                    for (int nt2 = 0; nt2 < 2; nt2++) {
                        mma16816(acc[mt][nt2 * 2 + 0], fal[mt], fbh[nt2][0], fbh[nt2][1]);
                        mma16816(acc[mt][nt2 * 2 + 1], fal[mt], fbh[nt2][2], fbh[nt2][3]);
                    }
            }
        }
    }

    // ---- epilogue (direct from c-fragments; no smem use, no final sync) ----
    int mbase = m0 + wm * 64 + (lane >> 2);
    int nbase = n0 + wn * 32 + (lane & 3) * 2;
#pragma unroll
    for (int nt = 0; nt < 4; nt++) {
        int n = nbase + nt * 8;
        float b0 = bias[n], b1 = bias[n + 1];
#pragma unroll
        for (int mt = 0; mt < 4; mt++) {
            int m = mbase + mt * 16;
            float v00 = acc[mt][nt][0] + b0, v01 = acc[mt][nt][1] + b1;
            float v10 = acc[mt][nt][2] + b0, v11 = acc[mt][nt][3] + b1;
            if (RELU) {
                v00 = fmaxf(v00, 0.0f); v01 = fmaxf(v01, 0.0f);
                v10 = fmaxf(v10, 0.0f); v11 = fmaxf(v11, 0.0f);
            }
            if (OUT == 1) {
                __half2 h2a, l2a, h2b, l2b;
                split2(v00, h2a.x, l2a.x); split2(v01, h2a.y, l2a.y);
                split2(v10, h2b.x, l2b.x); split2(v11, h2b.y, l2b.y);
                *(__half2*)(Ch + coff + (size_t)m * N + n)       = h2a;
                *(__half2*)(Cl + coff + (size_t)m * N + n)       = l2a;
                *(__half2*)(Ch + coff + (size_t)(m + 8) * N + n) = h2b;
                *(__half2*)(Cl + coff + (size_t)(m + 8) * N + n) = l2b;
            } else if (OUT == 2) {
                *(__half2*)(Ch + coff + (size_t)m * N + n) =
                    __floats2half2_rn(v00, v01);
                *(__half2*)(Ch + coff + (size_t)(m + 8) * N + n) =
                    __floats2half2_rn(v10, v11);
            } else {
                *(float2*)(Cf + coff + (size_t)m * N + n)       = make_float2(v00, v01);
                *(float2*)(Cf + coff + (size_t)(m + 8) * N + n) = make_float2(v10, v11);
            }
        }
    }
}

// ===================== attention: logits from hk, softmax, mixture ========
__global__ void attn_kernel(const int* __restrict__ task,
                            const __half* __restrict__ hkh,
                            const float* __restrict__ u,
                            const float* __restrict__ cvec,
                            const float* __restrict__ vals,
                            __half* __restrict__ tih,
                            __half* __restrict__ til,
                            float* __restrict__ loss_row) {
    int b = blockIdx.x;
    int tid = threadIdx.x;
    int wid = tid >> 5, lane = tid & 31;
    int t = task[b];

    float part[NE];
#pragma unroll
    for (int e = 0; e < NE; e++) part[e] = 0.0f;
    for (int h = tid; h < DH; h += 256) {
#pragma unroll
        for (int e = 0; e < NE; e++) {
            float hv_ = __half2float(hkh[((size_t)e * BSZ + b) * DH + h]);
            part[e] += hv_ * u[((size_t)e * NT + t) * DH + h];
        }
    }
#pragma unroll
    for (int e = 0; e < NE; e++) {
#pragma unroll
        for (int off = 16; off > 0; off >>= 1)
            part[e] += __shfl_down_sync(0xffffffffu, part[e], off);
    }
    __shared__ float warpsum[8][NE];
    __shared__ float attn_s[NE];
    if (lane == 0) {
#pragma unroll
        for (int e = 0; e < NE; e++) warpsum[wid][e] = part[e];
    }
    __syncthreads();
    if (tid == 0) {
        float logits[NE];
#pragma unroll
        for (int e = 0; e < NE; e++) {
            float s = cvec[e * NT + t];
            for (int w = 0; w < 8; w++) s += warpsum[w][e];
            logits[e] = s;
        }
        float mx = logits[0];
#pragma unroll
        for (int e = 1; e < NE; e++) mx = fmaxf(mx, logits[e]);
        float den = 0.0f, ex[NE];
#pragma unroll
        for (int e = 0; e < NE; e++) { ex[e] = expf(logits[e] - mx); den += ex[e]; }
        float inv = 1.0f / den;
        float lsum = 0.0f;
#pragma unroll
        for (int e = 0; e < NE; e++) {
            float a = ex[e] * inv;
            attn_s[e] = a;
            float lg = logf(a + 1e-10f);
            lg = fminf(fmaxf(lg, -6.0f), 0.0f);
            lsum += lg;
        }
        loss_row[b] = lsum;
    }
    __syncthreads();
    for (int k = tid; k < DKE; k += 256) {
        float acc = 0.0f;
#pragma unroll
        for (int e = 0; e < NE; e++)
            acc += attn_s[e] * vals[((size_t)e * BSZ + b) * DKE + k];
        __half h, l;
        split2(acc, h, l);
        tih[(size_t)b * DKE + k] = h;
        til[(size_t)b * DKE + k] = l;
    }
}

// ===================== q head + loss =====================================
__global__ void qhead_kernel(const float* __restrict__ h2,
                             const float* __restrict__ Wt2,
                             const float* __restrict__ bt2,
                             float* __restrict__ out) {
    int warp = (blockIdx.x * blockDim.x + threadIdx.x) >> 5;
    int lane = threadIdx.x & 31;
    if (warp >= BSZ) return;
    float s = 0.0f;
#pragma unroll
    for (int k = lane; k < 256; k += 32)
        s += h2[(size_t)warp * 256 + k] * Wt2[k];
#pragma unroll
    for (int off = 16; off > 0; off >>= 1)
        s += __shfl_down_sync(0xffffffffu, s, off);
    if (lane == 0) out[warp] = s + bt2[0];
}

__global__ void loss_kernel(const float* __restrict__ loss_row,
                            float* __restrict__ out, int out_size) {
    __shared__ float sm[256];
    int tid = threadIdx.x;
    float s = 0.0f;
    for (int i = tid; i < BSZ; i += 256) s += loss_row[i];
    sm[tid] = s;
    __syncthreads();
    for (int off = 128; off > 0; off >>= 1) {
        if (tid < off) sm[tid] += sm[tid + off];
        __syncthreads();
    }
    if (tid == 0 && out_size > BSZ)
        out[BSZ] = -(sm[0] / (float)BSZ) * 0.3f;
}

// ===================== launch =============================================
#define SYM(var, sym) cudaGetSymbolAddress((void**)&var, sym)

extern "C" void kernel_launch(void* const* d_in, const int* in_sizes, int n_in,
                              void* d_out, int out_size) {
    const float* state  = (const float*)d_in[0];
    const float* act    = (const float*)d_in[1];
    const float* rep_W0 = (const float*)d_in[2];
    const float* rep_b0 = (const float*)d_in[3];
    const float* rep_W1 = (const float*)d_in[4];
    const float* rep_b1 = (const float*)d_in[5];
    const float* emb    = (const float*)d_in[6];
    const float* Wk0    = (const float*)d_in[7];
    const float* bk0    = (const float*)d_in[8];
    const float* Wk1    = (const float*)d_in[9];
    const float* bk1    = (const float*)d_in[10];
    const float* Wv0    = (const float*)d_in[11];
    const float* bv0    = (const float*)d_in[12];
    const float* Wv1    = (const float*)d_in[13];
    const float* bv1    = (const float*)d_in[14];
    const float* Wt0    = (const float*)d_in[15];
    const float* bt0    = (const float*)d_in[16];
    const float* Wt1    = (const float*)d_in[17];
    const float* bt1    = (const float*)d_in[18];
    const float* Wt2    = (const float*)d_in[19];
    const float* bt2    = (const float*)d_in[20];
    float* out = (float*)d_out;

    __half *xh, *xl, *rhh, *rhl, *rsh, *rsl, *hkh, *hvh;
    __half *tih, *til, *h1h, *h1l;
    __half *W0h, *W0l, *W1h, *W1l, *Wk0h, *Wv0h;
    __half *Wv1h, *Wv1l, *Wt0h, *Wt0l, *Wt1h, *Wt1l;
    float *qtab, *u, *cvec, *vals, *h2, *lrow;
    int* task;
    SYM(xh, g_xh);   SYM(xl, g_xl);   SYM(task, g_task);
    SYM(qtab, g_qtab); SYM(u, g_u);   SYM(cvec, g_cvec);
    SYM(rhh, g_rhh); SYM(rhl, g_rhl); SYM(rsh, g_rsh); SYM(rsl, g_rsl);
    SYM(hkh, g_hkh); SYM(hvh, g_hvh);
    SYM(vals, g_vals);
    SYM(tih, g_tih); SYM(til, g_til); SYM(h1h, g_h1h); SYM(h1l, g_h1l);
    SYM(h2, g_h2);   SYM(lrow, g_lrow);
    SYM(W0h, g_W0h); SYM(W0l, g_W0l); SYM(W1h, g_W1h); SYM(W1l, g_W1l);
    SYM(Wk0h, g_Wk0h); SYM(Wv0h, g_Wv0h);
    SYM(Wv1h, g_Wv1h); SYM(Wv1l, g_Wv1l);
    SYM(Wt0h, g_Wt0h); SYM(Wt0l, g_Wt0l); SYM(Wt1h, g_Wt1h); SYM(Wt1l, g_Wt1l);

    cudaFuncSetAttribute(gemm_mma<true, true, true, 1>,   cudaFuncAttributeMaxDynamicSharedMemorySize, SM_REQ);
    cudaFuncSetAttribute(gemm_mma<true, true, false, 1>,  cudaFuncAttributeMaxDynamicSharedMemorySize, SM_REQ);
    cudaFuncSetAttribute(gemm_mma<false, false, true, 2>, cudaFuncAttributeMaxDynamicSharedMemorySize, SM_REQ);
    cudaFuncSetAttribute(gemm_mma<true, false, true, 2>,  cudaFuncAttributeMaxDynamicSharedMemorySize, SM_REQ);
    cudaFuncSetAttribute(gemm_mma<false, true, false, 0>, cudaFuncAttributeMaxDynamicSharedMemorySize, SM_REQ);
    cudaFuncSetAttribute(gemm_mma<true, true, true, 0>,   cudaFuncAttributeMaxDynamicSharedMemorySize, SM_REQ);

    // prep / precompute
    prep_kernel<<<BSZ, 256>>>(state, act, xh, xl, task);
    qtab_kernel<<<NT, 256>>>(emb, qtab);
    upre_kernel<<<dim3(DH / 8, NE * NT), 256>>>(Wk1, qtab, u);
    cvec_kernel<<<dim3(NE, NT), 256>>>(bk1, qtab, cvec);
    wtrans_all<<<42944, dim3(32, 8)>>>(
        rep_W0, rep_W1, Wk0, Wv0, Wv1, Wt0, Wt1,
        W0h, W0l, W1h, W1l, Wk0h, Wv0h, Wv1h, Wv1l,
        Wt0h, Wt0l, Wt1h, Wt1l);

    // rep MLP (exact 3-pass, split out)
    gemm_mma<true, true, true, 1><<<dim3(DREP / 128, BSZ / 128, 1), 256, SM_REQ>>>(
        xh, xl, W0h, W0l, rep_b0, nullptr, rhh, rhl, DREP, XD, 0, 0, 0, 0);
    gemm_mma<true, true, false, 1><<<dim3(DREP / 128, BSZ / 128, 1), 256, SM_REQ>>>(
        rhh, rhl, W1h, W1l, rep_b1, nullptr, rsh, rsl, DREP, DREP, 0, 0, 0, 0);
    // expert layer 1:
    //  K (logits path, error-damped by softmax): 1-pass pure fp16
    gemm_mma<false, false, true, 2><<<dim3(DH / 128, BSZ / 128, NE), 256, SM_REQ>>>(
        rsh, nullptr, Wk0h, nullptr, bk0, nullptr, hkh, nullptr, DH, DREP,
        0, (long)DH * DREP, DH, (long)BSZ * DH);
    //  V (value path): 2-pass A-split -> single fp16 hv
    gemm_mma<true, false, true, 2><<<dim3(DH / 128, BSZ / 128, NE), 256, SM_REQ>>>(
        rsh, rsl, Wv0h, nullptr, bv0, nullptr, hvh, nullptr, DH, DREP,
        0, (long)DH * DREP, DH, (long)BSZ * DH);
    // expert layer 2, V only: 2-pass B-split (hv single, Wv1 exact) -> fp32 vals
    gemm_mma<false, true, false, 0><<<dim3(DKE / 128, BSZ / 128, NE), 256, SM_REQ>>>(
        hvh, nullptr, Wv1h, Wv1l, bv1, vals, nullptr, nullptr, DKE, DH,
        (long)BSZ * DH, (long)DKE * DH, DKE, (long)BSZ * DKE);
    // attention: logits from hk via u, softmax, mixture
    attn_kernel<<<BSZ, 256>>>(task, hkh, u, cvec, vals, tih, til, lrow);
    // tower (exact 3-pass)
    gemm_mma<true, true, true, 1><<<dim3(512 / 128, BSZ / 128, 1), 256, SM_REQ>>>(
        tih, til, Wt0h, Wt0l, bt0, nullptr, h1h, h1l, 512, DKE, 0, 0, 0, 0);
    gemm_mma<true, true, true, 0><<<dim3(256 / 128, BSZ / 128, 1), 256, SM_REQ>>>(
        h1h, h1l, Wt1h, Wt1l, bt1, h2, nullptr, nullptr, 256, 512, 0, 0, 0, 0);
    // head + loss
    qhead_kernel<<<(BSZ * 32 + 255) / 256, 256>>>(h2, Wt2, bt2, out);
    loss_kernel<<<1, 256>>>(lrow, out, out_size);
}

// round 17
// speedup vs baseline: 1.2827x; 1.1141x over previous
#include <cuda_runtime.h>
#include <cuda_fp16.h>
#include <cstdint>
#include <math.h>

// Problem constants
#define BSZ   4096
#define OBS   512
#define ACT_D 64
#define NT    10
#define NE    16
#define DREP  1024
#define DH    1024
#define DKE   512
#define XD    (OBS + ACT_D)   // 576
#define SW    (OBS + NT)      // 522
#define KBIG  (NE * DH)       // 16384

// ===================== helpers =====================
__device__ __forceinline__ uint32_t smem_u32(const void* p) {
    uint32_t a;
    asm("{ .reg .u64 t; cvta.to.shared.u64 t, %1; cvt.u32.u64 %0, t; }"
        : "=r"(a) : "l"(p));
    return a;
}
__device__ __forceinline__ void cp16(uint32_t dst, const void* src) {
    asm volatile("cp.async.cg.shared.global [%0], [%1], 16;" :: "r"(dst), "l"(src));
}
#define CP_COMMIT() asm volatile("cp.async.commit_group;" ::: "memory")
#define CP_WAIT1()  asm volatile("cp.async.wait_group 1;" ::: "memory")

__device__ __forceinline__ void ldsm4(uint32_t* r, uint32_t addr) {
    asm volatile("ldmatrix.sync.aligned.m8n8.x4.shared.b16 {%0,%1,%2,%3}, [%4];"
                 : "=r"(r[0]), "=r"(r[1]), "=r"(r[2]), "=r"(r[3]) : "r"(addr));
}
// fp16 MMA, fp32 accumulate
__device__ __forceinline__ void mma16816(float* d, const uint32_t* a,
                                         uint32_t b0, uint32_t b1) {
    asm volatile(
        "mma.sync.aligned.m16n8k16.row.col.f32.f16.f16.f32 "
        "{%0,%1,%2,%3}, {%4,%5,%6,%7}, {%8,%9}, {%0,%1,%2,%3};"
        : "+f"(d[0]), "+f"(d[1]), "+f"(d[2]), "+f"(d[3])
        : "r"(a[0]), "r"(a[1]), "r"(a[2]), "r"(a[3]), "r"(b0), "r"(b1));
}

__device__ __forceinline__ void split2(float v, __half& h, __half& l) {
    h = __float2half(v);
    l = __float2half(v - __half2float(h));
}

// ===================== scratch (static device globals) =====================
__device__ __half g_xh[(size_t)BSZ * XD], g_xl[(size_t)BSZ * XD];
__device__ int   g_task[BSZ];
__device__ float g_qtab[NT * DKE];
__device__ float g_u[(size_t)NE * NT * DH];
__device__ float g_cvec[NE * NT];
__device__ __half g_rhh[(size_t)BSZ * DREP], g_rhl[(size_t)BSZ * DREP];
__device__ __half g_rsh[(size_t)BSZ * DREP], g_rsl[(size_t)BSZ * DREP];
__device__ __half g_hkh[(size_t)NE * BSZ * DH];           // [e][b][h]
__device__ __half g_hvp[(size_t)BSZ * KBIG];              // attn-scaled hv: [b][e*DH+h]
__device__ float g_attn[(size_t)BSZ * NE];
__device__ float g_tpart[(size_t)4 * BSZ * DKE];          // 4 e-group partials
__device__ float g_zbias[DKE];                            // stays zero
__device__ __half g_tih[(size_t)BSZ * DKE], g_til[(size_t)BSZ * DKE];
__device__ __half g_h1h[(size_t)BSZ * 512], g_h1l[(size_t)BSZ * 512];
__device__ float g_h2[(size_t)BSZ * 256];
__device__ float g_lrow[BSZ];
// transposed split weights ([N,K] fp16)
__device__ __half g_W0h[(size_t)DREP * XD],  g_W0l[(size_t)DREP * XD];
__device__ __half g_W1h[(size_t)DREP * DREP], g_W1l[(size_t)DREP * DREP];
__device__ __half g_Wk0h[(size_t)NE * DH * DREP];         // h only
__device__ __half g_Wv0h[(size_t)NE * DH * DREP];         // h only
__device__ __half g_Wv1t[(size_t)DKE * KBIG];             // [n][e*DH+h], h only
__device__ __half g_Wt0h[(size_t)512 * DKE], g_Wt0l[(size_t)512 * DKE];
__device__ __half g_Wt1h[(size_t)256 * 512], g_Wt1l[(size_t)256 * 512];

// ===================== prep: x split + task id ============================
__global__ void prep_kernel(const float* __restrict__ state,
                            const float* __restrict__ act,
                            __half* __restrict__ xh,
                            __half* __restrict__ xl,
                            int* __restrict__ task) {
    int b = blockIdx.x;
    int tid = threadIdx.x;
    for (int i = tid; i < XD; i += blockDim.x) {
        float v = (i < OBS) ? state[(size_t)b * SW + i] : act[(size_t)b * ACT_D + (i - OBS)];
        __half h, l;
        split2(v, h, l);
        xh[(size_t)b * XD + i] = h;
        xl[(size_t)b * XD + i] = l;
    }
    if (tid == 0) {
        float best = -1e30f; int idx = 0;
        for (int t = 0; t < NT; t++) {
            float v = state[(size_t)b * SW + OBS + t];
            if (v > best) { best = v; idx = t; }
        }
        task[b] = idx;
    }
}

// qtab[t][k] = tanh(emb[t][k])
__global__ void qtab_kernel(const float* __restrict__ emb, float* __restrict__ qtab) {
    int t = blockIdx.x;
    for (int k = threadIdx.x; k < DKE; k += blockDim.x)
        qtab[t * DKE + k] = tanhf(emb[t * DKE + k]);
}

// u[e][t][h] = sum_k Wk1[e][h][k] * qtab[t][k]
__global__ void upre_kernel(const float* __restrict__ Wk1,
                            const float* __restrict__ qtab,
                            float* __restrict__ u) {
    int z = blockIdx.y;               // e*NT + t
    int e = z / NT, t = z % NT;
    int wid = threadIdx.x >> 5, lane = threadIdx.x & 31;
    int h = blockIdx.x * 8 + wid;     // gridDim.x = DH/8
    const float* wr = Wk1 + ((size_t)e * DH + h) * DKE;
    const float* qr = qtab + t * DKE;
    float s = 0.0f;
#pragma unroll 4
    for (int k = lane; k < DKE; k += 32) s += wr[k] * qr[k];
#pragma unroll
    for (int off = 16; off > 0; off >>= 1) s += __shfl_down_sync(0xffffffffu, s, off);
    if (lane == 0) u[((size_t)e * NT + t) * DH + h] = s;
}

// cvec[e][t] = sum_k bk1[e][k] * qtab[t][k]
__global__ void cvec_kernel(const float* __restrict__ bk1,
                            const float* __restrict__ qtab,
                            float* __restrict__ cvec) {
    int e = blockIdx.x, t = blockIdx.y;
    __shared__ float sm[256];
    int tid = threadIdx.x;
    float s = 0.0f;
    for (int k = tid; k < DKE; k += 256) s += bk1[e * DKE + k] * qtab[t * DKE + k];
    sm[tid] = s;
    __syncthreads();
    for (int off = 128; off > 0; off >>= 1) {
        if (tid < off) sm[tid] += sm[tid + off];
        __syncthreads();
    }
    if (tid == 0) cvec[e * NT + t] = sm[0];
}

// ===================== ALL weight transposes in ONE launch ================
// Tile counts: W0 576 | W1 1024 | Wk0 16384 | Wv0 16384 | Wv1 8192
//              Wt0 256 | Wt1 128   (total 42944).  Wk1 handled by upre.
// Wv1 is written h-only into the stacked layout [n][e*DH + h].
__global__ void wtrans_all(
    const float* __restrict__ W0, const float* __restrict__ W1,
    const float* __restrict__ Wk0, const float* __restrict__ Wv0,
    const float* __restrict__ Wv1,
    const float* __restrict__ Wt0, const float* __restrict__ Wt1,
    __half* W0h, __half* W0l, __half* W1h, __half* W1l,
    __half* Wk0h, __half* Wv0h, __half* Wv1t,
    __half* Wt0h, __half* Wt0l, __half* Wt1h, __half* Wt1l) {
    int t = blockIdx.x;
    const float* W; __half *Th, *Tl; int K, N;
    size_t ostride, zoff;
    bool stacked = false;
    if (t < 576)                  { W = W0;  Th = W0h;  Tl = W0l;  K = XD;   N = DREP; }
    else if ((t -= 576) < 1024)   { W = W1;  Th = W1h;  Tl = W1l;  K = DREP; N = DREP; }
    else if ((t -= 1024) < 16384) { W = Wk0; Th = Wk0h; Tl = nullptr; K = DREP; N = DH; }
    else if ((t -= 16384) < 16384){ W = Wv0; Th = Wv0h; Tl = nullptr; K = DREP; N = DH; }
    else if ((t -= 16384) < 8192) { W = Wv1; Th = Wv1t; Tl = nullptr; K = DH;  N = DKE; stacked = true; }
    else if ((t -= 8192) < 256)   { W = Wt0; Th = Wt0h; Tl = Wt0l; K = DKE;  N = 512; }
    else                          { t -= 256; W = Wt1; Th = Wt1h; Tl = Wt1l; K = 512; N = 256; }
    int tpm = (K >> 5) * (N >> 5);
    int z = t / tpm, r = t % tpm;
    int kt = r / (N >> 5), nt = r % (N >> 5);
    W  += (size_t)z * K * N;
    if (stacked) { ostride = KBIG; zoff = (size_t)z * DH; }
    else         { ostride = K;    zoff = (size_t)z * K * N; }

    __shared__ float tsm[32][33];
    int n0 = nt * 32, k0 = kt * 32;
    int tx = threadIdx.x, ty = threadIdx.y;
    for (int i = ty; i < 32; i += 8)
        tsm[i][tx] = W[(size_t)(k0 + i) * N + n0 + tx];
    __syncthreads();
    for (int i = ty; i < 32; i += 8) {
        float v = tsm[tx][i];
        __half h = __float2half(v);
        Th[(size_t)(n0 + i) * ostride + zoff + k0 + tx] = h;
        if (Tl) Tl[(size_t)(n0 + i) * ostride + zoff + k0 + tx] =
            __float2half(v - __half2float(h));
    }
}

// ===================== mma.sync split-fp16 GEMM ============================
// Passes: AhBh always; +AhBl if BSPL; +AlBh if ASPL.
// OUT: 0 = fp32 Cf, 1 = split (Ch, Cl), 2 = single fp16 Ch
// SCALE: multiply epilogue by scale[m*NE + blockIdx.z] (after bias+relu).
// lda/ldb/ldc: element row strides of A, B, C (decoupled from N, K).
// One barrier per k-chunk; 3-stage cp.async pipeline; 2 CTAs/SM.

#define STG 32768            // Ah 8K | Al 8K | Bh 8K | Bl 8K
#define OFF_AH 0
#define OFF_AL 8192
#define OFF_BH 16384
#define OFF_BL 24576
#define SM_REQ (3 * STG)

__device__ __forceinline__ uint32_t swz(int r, int c) {
    return (uint32_t)(r * 64 + ((c ^ ((r >> 1) & 3)) << 4));
}

template <bool ASPL, bool BSPL, bool RELU, int OUT, bool SCALE>
__global__ void __launch_bounds__(256, 2)
gemm_mma(const __half* __restrict__ Ah, const __half* __restrict__ Al,
         const __half* __restrict__ Bh, const __half* __restrict__ Bl,
         const float* __restrict__ bias, const float* __restrict__ scale,
         float* __restrict__ Cf, __half* __restrict__ Ch, __half* __restrict__ Cl,
         int N, int K, int lda, int ldb, int ldc,
         long sA, long sB, long sBias, long sC) {
    extern __shared__ char sm_raw[];
    uint32_t sb = smem_u32(sm_raw);

    int tid = threadIdx.x, lane = tid & 31, wid = tid >> 5;
    int z = blockIdx.z;
    const char* aH = (const char*)(Ah + (size_t)z * sA);
    const char* aL = ASPL ? (const char*)(Al + (size_t)z * sA) : nullptr;
    const char* bH = (const char*)(Bh + (size_t)z * sB);
    const char* bL = BSPL ? (const char*)(Bl + (size_t)z * sB) : nullptr;
    bias += (size_t)z * sBias;
    size_t coff = (size_t)z * sC;

    int m0 = blockIdx.y * 128, n0 = blockIdx.x * 128;
    int wm = wid & 1, wn = wid >> 1;       // 2 x 4 warps, warp tile 64x32

    size_t rsbA = (size_t)lda * 2, rsbB = (size_t)ldb * 2;
    aH += (size_t)m0 * rsbA;
    if (ASPL) aL += (size_t)m0 * rsbA;
    bH += (size_t)n0 * rsbB;
    if (BSPL) bL += (size_t)n0 * rsbB;

    float acc[4][4][4];
#pragma unroll
    for (int i = 0; i < 4; i++)
#pragma unroll
        for (int j = 0; j < 4; j++)
#pragma unroll
            for (int q = 0; q < 4; q++) acc[i][j][q] = 0.0f;

    int NC = K >> 5;

    auto load_stage = [&](int c, int buf) {
        uint32_t s = sb + buf * STG;
        size_t gk = (size_t)c * 64;
#pragma unroll
        for (int p = tid; p < 512; p += 256) {
            int r = p >> 2, ch = p & 3;
            uint32_t off = swz(r, ch);
            size_t gA = (size_t)r * rsbA + gk + ch * 16;
            size_t gB = (size_t)r * rsbB + gk + ch * 16;
            cp16(s + OFF_AH + off, aH + gA);
            if (ASPL) cp16(s + OFF_AL + off, aL + gA);
            cp16(s + OFF_BH + off, bH + gB);
            if (BSPL) cp16(s + OFF_BL + off, bL + gB);
        }
    };

    load_stage(0, 0); CP_COMMIT();
    load_stage(1, 1); CP_COMMIT();

    int arow = wm * 64 + (lane & 7) + ((lane >> 3) & 1) * 8;
    int achk_b = (lane >> 4);
    int brow = wn * 32 + (lane & 7) + (lane >> 4) * 8;
    int bchk_b = ((lane >> 3) & 1);

    for (int c = 0; c < NC; c++) {
        CP_WAIT1();
        __syncthreads();
        if (c + 2 < NC) load_stage(c + 2, (c + 2) % 3);
        CP_COMMIT();

        uint32_t s = sb + (c % 3) * STG;
#pragma unroll
        for (int ks = 0; ks < 2; ks++) {
            int achk = ks * 2 + achk_b;
            int bchk = ks * 2 + bchk_b;
            uint32_t fah[4][4], fbh[2][4];
#pragma unroll
            for (int mt = 0; mt < 4; mt++)
                ldsm4(fah[mt], s + OFF_AH + swz(arow + mt * 16, achk));
#pragma unroll
            for (int nt2 = 0; nt2 < 2; nt2++)
                ldsm4(fbh[nt2], s + OFF_BH + swz(brow + nt2 * 16, bchk));
#pragma unroll
            for (int mt = 0; mt < 4; mt++)
#pragma unroll
                for (int nt2 = 0; nt2 < 2; nt2++) {
                    mma16816(acc[mt][nt2 * 2 + 0], fah[mt], fbh[nt2][0], fbh[nt2][1]);
                    mma16816(acc[mt][nt2 * 2 + 1], fah[mt], fbh[nt2][2], fbh[nt2][3]);
                }
            if (BSPL) {
                uint32_t fbl[2][4];
#pragma unroll
                for (int nt2 = 0; nt2 < 2; nt2++)
                    ldsm4(fbl[nt2], s + OFF_BL + swz(brow + nt2 * 16, bchk));
#pragma unroll
                for (int mt = 0; mt < 4; mt++)
#pragma unroll
                    for (int nt2 = 0; nt2 < 2; nt2++) {
                        mma16816(acc[mt][nt2 * 2 + 0], fah[mt], fbl[nt2][0], fbl[nt2][1]);
                        mma16816(acc[mt][nt2 * 2 + 1], fah[mt], fbl[nt2][2], fbl[nt2][3]);
                    }
            }
            if (ASPL) {
                uint32_t fal[4][4];
#pragma unroll
                for (int mt = 0; mt < 4; mt++)
                    ldsm4(fal[mt], s + OFF_AL + swz(arow + mt * 16, achk));
#pragma unroll
                for (int mt = 0; mt < 4; mt++)
#pragma unroll
                    for (int nt2 = 0; nt2 < 2; nt2++) {
                        mma16816(acc[mt][nt2 * 2 + 0], fal[mt], fbh[nt2][0], fbh[nt2][1]);
                        mma16816(acc[mt][nt2 * 2 + 1], fal[mt], fbh[nt2][2], fbh[nt2][3]);
                    }
            }
        }
    }

    // ---- epilogue ----
    int mbase = m0 + wm * 64 + (lane >> 2);
    int nbase = n0 + wn * 32 + (lane & 3) * 2;
#pragma unroll
    for (int mt = 0; mt < 4; mt++) {
        int m = mbase + mt * 16;
        float sc0 = 1.0f, sc1 = 1.0f;
        if (SCALE) {
            sc0 = scale[(size_t)m * NE + z];
            sc1 = scale[(size_t)(m + 8) * NE + z];
        }
#pragma unroll
        for (int nt = 0; nt < 4; nt++) {
            int n = nbase + nt * 8;
            float b0 = bias[n], b1 = bias[n + 1];
            float v00 = acc[mt][nt][0] + b0, v01 = acc[mt][nt][1] + b1;
            float v10 = acc[mt][nt][2] + b0, v11 = acc[mt][nt][3] + b1;
            if (RELU) {
                v00 = fmaxf(v00, 0.0f); v01 = fmaxf(v01, 0.0f);
                v10 = fmaxf(v10, 0.0f); v11 = fmaxf(v11, 0.0f);
            }
            if (SCALE) { v00 *= sc0; v01 *= sc0; v10 *= sc1; v11 *= sc1; }
            size_t i0 = coff + (size_t)m * ldc + n;
            size_t i1 = coff + (size_t)(m + 8) * ldc + n;
            if (OUT == 1) {
                __half2 h2a, l2a, h2b, l2b;
                split2(v00, h2a.x, l2a.x); split2(v01, h2a.y, l2a.y);
                split2(v10, h2b.x, l2b.x); split2(v11, h2b.y, l2b.y);
                *(__half2*)(Ch + i0) = h2a;
                *(__half2*)(Cl + i0) = l2a;
                *(__half2*)(Ch + i1) = h2b;
                *(__half2*)(Cl + i1) = l2b;
            } else if (OUT == 2) {
                *(__half2*)(Ch + i0) = __floats2half2_rn(v00, v01);
                *(__half2*)(Ch + i1) = __floats2half2_rn(v10, v11);
            } else {
                *(float2*)(Cf + i0) = make_float2(v00, v01);
                *(float2*)(Cf + i1) = make_float2(v10, v11);
            }
        }
    }
}

// ===================== attention weights: logits -> softmax ===============
__global__ void attnw_kernel(const int* __restrict__ task,
                             const __half* __restrict__ hkh,
                             const float* __restrict__ u,
                             const float* __restrict__ cvec,
                             float* __restrict__ attn,
                             float* __restrict__ loss_row) {
    int b = blockIdx.x;
    int tid = threadIdx.x;
    int wid = tid >> 5, lane = tid & 31;
    int t = task[b];

    float part[NE];
#pragma unroll
    for (int e = 0; e < NE; e++) part[e] = 0.0f;
    for (int h = tid; h < DH; h += 256) {
#pragma unroll
        for (int e = 0; e < NE; e++) {
            float hv_ = __half2float(hkh[((size_t)e * BSZ + b) * DH + h]);
            part[e] += hv_ * u[((size_t)e * NT + t) * DH + h];
        }
    }
#pragma unroll
    for (int e = 0; e < NE; e++) {
#pragma unroll
        for (int off = 16; off > 0; off >>= 1)
            part[e] += __shfl_down_sync(0xffffffffu, part[e], off);
    }
    __shared__ float warpsum[8][NE];
    if (lane == 0) {
#pragma unroll
        for (int e = 0; e < NE; e++) warpsum[wid][e] = part[e];
    }
    __syncthreads();
    if (tid == 0) {
        float logits[NE];
#pragma unroll
        for (int e = 0; e < NE; e++) {
            float s = cvec[e * NT + t];
            for (int w = 0; w < 8; w++) s += warpsum[w][e];
            logits[e] = s;
        }
        float mx = logits[0];
#pragma unroll
        for (int e = 1; e < NE; e++) mx = fmaxf(mx, logits[e]);
        float den = 0.0f, ex[NE];
#pragma unroll
        for (int e = 0; e < NE; e++) { ex[e] = expf(logits[e] - mx); den += ex[e]; }
        float inv = 1.0f / den;
        float lsum = 0.0f;
#pragma unroll
        for (int e = 0; e < NE; e++) {
            float a = ex[e] * inv;
            attn[(size_t)b * NE + e] = a;
            float lg = logf(a + 1e-10f);
            lg = fminf(fmaxf(lg, -6.0f), 0.0f);
            lsum += lg;
        }
        loss_row[b] = lsum;
    }
}

// ===================== reduce partials + attn-weighted bv1 ================
__global__ void reduce_kernel(const float* __restrict__ tpart,
                              const float* __restrict__ attn,
                              const float* __restrict__ bv1,
                              __half* __restrict__ tih,
                              __half* __restrict__ til) {
    int b = blockIdx.x;
    int tid = threadIdx.x;
    __shared__ float asm_[NE];
    if (tid < NE) asm_[tid] = attn[(size_t)b * NE + tid];
    __syncthreads();
    for (int k = tid; k < DKE; k += 256) {
        float s = 0.0f;
#pragma unroll
        for (int g = 0; g < 4; g++)
            s += tpart[((size_t)g * BSZ + b) * DKE + k];
#pragma unroll
        for (int e = 0; e < NE; e++)
            s += asm_[e] * bv1[e * DKE + k];
        __half h, l;
        split2(s, h, l);
        tih[(size_t)b * DKE + k] = h;
        til[(size_t)b * DKE + k] = l;
    }
}

// ===================== q head + loss =====================================
__global__ void qhead_kernel(const float* __restrict__ h2,
                             const float* __restrict__ Wt2,
                             const float* __restrict__ bt2,
                             float* __restrict__ out) {
    int warp = (blockIdx.x * blockDim.x + threadIdx.x) >> 5;
    int lane = threadIdx.x & 31;
    if (warp >= BSZ) return;
    float s = 0.0f;
#pragma unroll
    for (int k = lane; k < 256; k += 32)
        s += h2[(size_t)warp * 256 + k] * Wt2[k];
#pragma unroll
    for (int off = 16; off > 0; off >>= 1)
        s += __shfl_down_sync(0xffffffffu, s, off);
    if (lane == 0) out[warp] = s + bt2[0];
}

__global__ void loss_kernel(const float* __restrict__ loss_row,
                            float* __restrict__ out, int out_size) {
    __shared__ float sm[256];
    int tid = threadIdx.x;
    float s = 0.0f;
    for (int i = tid; i < BSZ; i += 256) s += loss_row[i];
    sm[tid] = s;
    __syncthreads();
    for (int off = 128; off > 0; off >>= 1) {
        if (tid < off) sm[tid] += sm[tid + off];
        __syncthreads();
    }
    if (tid == 0 && out_size > BSZ)
        out[BSZ] = -(sm[0] / (float)BSZ) * 0.3f;
}

// ===================== launch =============================================
#define SYM(var, sym) cudaGetSymbolAddress((void**)&var, sym)

extern "C" void kernel_launch(void* const* d_in, const int* in_sizes, int n_in,
                              void* d_out, int out_size) {
    const float* state  = (const float*)d_in[0];
    const float* act    = (const float*)d_in[1];
    const float* rep_W0 = (const float*)d_in[2];
    const float* rep_b0 = (const float*)d_in[3];
    const float* rep_W1 = (const float*)d_in[4];
    const float* rep_b1 = (const float*)d_in[5];
    const float* emb    = (const float*)d_in[6];
    const float* Wk0    = (const float*)d_in[7];
    const float* bk0    = (const float*)d_in[8];
    const float* Wk1    = (const float*)d_in[9];
    const float* bk1    = (const float*)d_in[10];
    const float* Wv0    = (const float*)d_in[11];
    const float* bv0    = (const float*)d_in[12];
    const float* Wv1    = (const float*)d_in[13];
    const float* bv1    = (const float*)d_in[14];
    const float* Wt0    = (const float*)d_in[15];
    const float* bt0    = (const float*)d_in[16];
    const float* Wt1    = (const float*)d_in[17];
    const float* bt1    = (const float*)d_in[18];
    const float* Wt2    = (const float*)d_in[19];
    const float* bt2    = (const float*)d_in[20];
    float* out = (float*)d_out;

    __half *xh, *xl, *rhh, *rhl, *rsh, *rsl, *hkh, *hvp;
    __half *tih, *til, *h1h, *h1l;
    __half *W0h, *W0l, *W1h, *W1l, *Wk0h, *Wv0h, *Wv1t;
    __half *Wt0h, *Wt0l, *Wt1h, *Wt1l;
    float *qtab, *u, *cvec, *attn, *tpart, *zbias, *h2, *lrow;
    int* task;
    SYM(xh, g_xh);   SYM(xl, g_xl);   SYM(task, g_task);
    SYM(qtab, g_qtab); SYM(u, g_u);   SYM(cvec, g_cvec);
    SYM(rhh, g_rhh); SYM(rhl, g_rhl); SYM(rsh, g_rsh); SYM(rsl, g_rsl);
    SYM(hkh, g_hkh); SYM(hvp, g_hvp);
    SYM(attn, g_attn); SYM(tpart, g_tpart); SYM(zbias, g_zbias);
    SYM(tih, g_tih); SYM(til, g_til); SYM(h1h, g_h1h); SYM(h1l, g_h1l);
    SYM(h2, g_h2);   SYM(lrow, g_lrow);
    SYM(W0h, g_W0h); SYM(W0l, g_W0l); SYM(W1h, g_W1h); SYM(W1l, g_W1l);
    SYM(Wk0h, g_Wk0h); SYM(Wv0h, g_Wv0h); SYM(Wv1t, g_Wv1t);
    SYM(Wt0h, g_Wt0h); SYM(Wt0l, g_Wt0l); SYM(Wt1h, g_Wt1h); SYM(Wt1l, g_Wt1l);

    cudaFuncSetAttribute(gemm_mma<true, true, true, 1, false>,   cudaFuncAttributeMaxDynamicSharedMemorySize, SM_REQ);
    cudaFuncSetAttribute(gemm_mma<true, true, false, 1, false>,  cudaFuncAttributeMaxDynamicSharedMemorySize, SM_REQ);
    cudaFuncSetAttribute(gemm_mma<false, false, true, 2, false>, cudaFuncAttributeMaxDynamicSharedMemorySize, SM_REQ);
    cudaFuncSetAttribute(gemm_mma<true, false, true, 2, true>,   cudaFuncAttributeMaxDynamicSharedMemorySize, SM_REQ);
    cudaFuncSetAttribute(gemm_mma<false, false, false, 0, false>,cudaFuncAttributeMaxDynamicSharedMemorySize, SM_REQ);
    cudaFuncSetAttribute(gemm_mma<true, true, true, 0, false>,   cudaFuncAttributeMaxDynamicSharedMemorySize, SM_REQ);

    // prep / precompute
    prep_kernel<<<BSZ, 256>>>(state, act, xh, xl, task);
    qtab_kernel<<<NT, 256>>>(emb, qtab);
    upre_kernel<<<dim3(DH / 8, NE * NT), 256>>>(Wk1, qtab, u);
    cvec_kernel<<<dim3(NE, NT), 256>>>(bk1, qtab, cvec);
    wtrans_all<<<42944, dim3(32, 8)>>>(
        rep_W0, rep_W1, Wk0, Wv0, Wv1, Wt0, Wt1,
        W0h, W0l, W1h, W1l, Wk0h, Wv0h, Wv1t,
        Wt0h, Wt0l, Wt1h, Wt1l);

    // rep MLP (exact 3-pass, split out)
    gemm_mma<true, true, true, 1, false><<<dim3(DREP / 128, BSZ / 128, 1), 256, SM_REQ>>>(
        xh, xl, W0h, W0l, rep_b0, nullptr, nullptr, rhh, rhl,
        DREP, XD, XD, XD, DREP, 0, 0, 0, 0);
    gemm_mma<true, true, false, 1, false><<<dim3(DREP / 128, BSZ / 128, 1), 256, SM_REQ>>>(
        rhh, rhl, W1h, W1l, rep_b1, nullptr, nullptr, rsh, rsl,
        DREP, DREP, DREP, DREP, DREP, 0, 0, 0, 0);
    // expert layer 1 K (logits path): 1-pass pure fp16 -> hkh [e][b][h]
    gemm_mma<false, false, true, 2, false><<<dim3(DH / 128, BSZ / 128, NE), 256, SM_REQ>>>(
        rsh, nullptr, Wk0h, nullptr, bk0, nullptr, nullptr, hkh, nullptr,
        DH, DREP, DREP, DREP, DH, 0, (long)DH * DREP, DH, (long)BSZ * DH);
    // attention weights + loss (needs only hk)
    attnw_kernel<<<BSZ, 256>>>(task, hkh, u, cvec, attn, lrow);
    // expert layer 1 V: 2-pass A-split, epilogue scaled by attn -> hvp [b][e*DH+h]
    gemm_mma<true, false, true, 2, true><<<dim3(DH / 128, BSZ / 128, NE), 256, SM_REQ>>>(
        rsh, rsl, Wv0h, nullptr, bv0, attn, nullptr, hvp, nullptr,
        DH, DREP, DREP, DREP, KBIG, 0, (long)DH * DREP, DH, DH);
    // expert layer 2 V: big-K fused mixture, 1-pass, e-split into 4 groups
    gemm_mma<false, false, false, 0, false><<<dim3(DKE / 128, BSZ / 128, 4), 256, SM_REQ>>>(
        hvp, nullptr, Wv1t, nullptr, zbias, nullptr, tpart, nullptr, nullptr,
        DKE, 4096, KBIG, KBIG, DKE, 4096, 4096, 0, (long)BSZ * DKE);
    // reduce partials + attn-weighted bv1 -> split tower input
    reduce_kernel<<<BSZ, 256>>>(tpart, attn, bv1, tih, til);
    // tower (exact 3-pass)
    gemm_mma<true, true, true, 1, false><<<dim3(512 / 128, BSZ / 128, 1), 256, SM_REQ>>>(
        tih, til, Wt0h, Wt0l, bt0, nullptr, nullptr, h1h, h1l,
        512, DKE, DKE, DKE, 512, 0, 0, 0, 0);
    gemm_mma<true, true, true, 0, false><<<dim3(256 / 128, BSZ / 128, 1), 256, SM_REQ>>>(
        h1h, h1l, Wt1h, Wt1l, bt1, nullptr, h2, nullptr, nullptr,
        256, 512, 512, 512, 256, 0, 0, 0, 0);
    // head + loss
    qhead_kernel<<<(BSZ * 32 + 255) / 256, 256>>>(h2, Wt2, bt2, out);
    loss_kernel<<<1, 256>>>(lrow, out, out_size);
}